// round 3
// baseline (speedup 1.0000x reference)
#include <cuda_runtime.h>
#include <math_constants.h>

// Problem constants
#define B_      256
#define N_      16
#define M_      128
#define V_      64
#define H_      256
#define K_      8
#define NP1_    17      // N + 1
#define KO_     136     // K * (N+1)
#define TYPES_  12
#define NT      544     // 136 outputs x 4 H-quadrants

// Output layout: new_d [B,M,V] floats, then new_v [B,40,3,V] zeros
#define OUT_D_ELEMS ((size_t)B_ * M_ * V_)
#define OUT_V_PER_B (40 * 3 * V_)   // 7680 floats per batch

__global__ __launch_bounds__(NT, 2)
void fused_kernel(
    const float* __restrict__ decodings,     // [B,N,M,V]
    const int*   __restrict__ target_types,  // [B]
    const int*   __restrict__ spans,         // [B]
    const float* __restrict__ te_table,      // [21,H]
    const float* __restrict__ W_sem,         // [15,12,H,KO]
    const float* __restrict__ b_sem,         // [15,12,KO]
    const float* __restrict__ gumbel,        // [B,K,NP1]
    float*       __restrict__ out)
{
    __shared__ float  s_te[H_];
    __shared__ double s_part[NT];
    __shared__ float  s_logit[KO_];
    __shared__ int    s_sel[K_];
    __shared__ int    s_red[16];
    __shared__ int    s_olen;

    const int b    = blockIdx.x;
    const int tid  = threadIdx.x;
    const int w    = tid >> 5;
    const int lane = tid & 31;

    // scalar control loads first (head of the dependency chain)
    const int tt = target_types[b];
    const int sp = spans[b];

    // gumbel preload — independent of tt/sp, flies during the GEMV chain
    float gval = 0.f;
    if (w < K_ && lane < NP1_)
        gval = __ldg(&gumbel[((size_t)b * K_ + w) * NP1_ + lane]);

    // new_v zero-fill — independent stores (half of all output bytes), issue early
    {
        const float4 z = make_float4(0.f, 0.f, 0.f, 0.f);
        float* __restrict__ dv = out + OUT_D_ELEMS + (size_t)b * OUT_V_PER_B;
        #pragma unroll
        for (int i = tid; i < OUT_V_PER_B / 4; i += NT)
            ((float4*)dv)[i] = z;
    }

    // ---------------- Phase 1: selection ----------------
    if (tt != 20) {
        if (tid < H_) s_te[tid] = te_table[(size_t)tt * H_ + tid];
        const int combo = (sp - 2) * TYPES_ + (tt - 9);
        __syncthreads();

        // 544 threads: output o = tid%136, H-quadrant q = tid/136 (64 h each).
        // 16 accumulators -> only 4 dependent load batches.
        const int o = tid % KO_;
        const int q = tid / KO_;
        double sum = 0.0;
        if ((o % NP1_) <= sp) {       // skip masked (invalid-n) columns entirely
            const float* __restrict__ wp =
                W_sem + ((size_t)combo * H_ + (size_t)(q * 64)) * KO_ + o;
            const float* __restrict__ tp = s_te + q * 64;
            float a[16];
            #pragma unroll
            for (int j = 0; j < 16; j++) a[j] = 0.f;
            #pragma unroll
            for (int h = 0; h < 64; h += 16) {
                #pragma unroll
                for (int j = 0; j < 16; j++)
                    a[j] = fmaf(tp[h + j], wp[(size_t)(h + j) * KO_], a[j]);
            }
            #pragma unroll
            for (int j = 0; j < 16; j += 2)
                sum += (double)a[j] + (double)a[j + 1];
        }
        s_part[tid] = sum;
        __syncthreads();

        if (tid < KO_) {
            double s = (s_part[tid] + s_part[tid + KO_])
                     + (s_part[tid + 2 * KO_] + s_part[tid + 3 * KO_]);
            s_logit[tid] = (float)s + __ldg(&b_sem[(size_t)combo * KO_ + tid]);
        }
        __syncthreads();

        // per-warp argmax over valid n of (logit + gumbel), warp w = template k
        if (w < K_) {
            float val = -CUDART_INF_F;
            if (lane < NP1_ && lane <= sp)
                val = s_logit[w * NP1_ + lane] + gval;
            float bv = val;
            int   bn = lane;
            #pragma unroll
            for (int off = 16; off; off >>= 1) {
                float ov = __shfl_down_sync(0xffffffffu, bv, off);
                int   on = __shfl_down_sync(0xffffffffu, bn, off);
                if (ov > bv || (ov == bv && on < bn)) { bv = ov; bn = on; }
            }
            if (lane == 0) s_sel[w] = bn;
        }
    } else {
        // fixed start template: k=0 -> decoding 0 (n=1), others -> pad
        if (tid < K_) s_sel[tid] = (tid == 0) ? 1 : 0;
    }
    __syncthreads();

    // ---------------- Phase 2: fused speculative copy + olen ----------------
    // Threads 0..511 copy; rows beyond olen get overwritten by the next
    // segment or the zero-fill (idx strictly increases -> exact semantics).
    const int c4    = tid & 15;         // float4 column (V=64 -> 16 float4/row)
    const int rbase = (tid >> 4) & 31;  // base row 0..31 (for tid < 512)
    int idx = 0;

    for (int k = 0; k < K_; k++) {
        if (idx >= M_) break;
        const int n = s_sel[k];
        if (n == 0) continue;

        if (tid < 512) {
            const float4* __restrict__ tile4 =
                (const float4*)(decodings + ((size_t)b * N_ + (size_t)(n - 1)) * (M_ * V_));
            float4* __restrict__ out4 =
                (float4*)(out + ((size_t)b * M_ + idx) * V_);

            float4 v[4];
            #pragma unroll
            for (int j = 0; j < 4; j++)
                v[j] = tile4[(rbase + 32 * j) * 16 + c4];

            int local = 0;
            #pragma unroll
            for (int j = 0; j < 4; j++) {
                const int row = rbase + 32 * j;
                if (idx + row < M_)
                    out4[row * 16 + c4] = v[j];
                // row non-pad iff max over v>0 of d[row][v] > d[row][0]
                float m = (c4 == 0) ? fmaxf(fmaxf(v[j].y, v[j].z), v[j].w)
                                    : fmaxf(fmaxf(v[j].x, v[j].y), fmaxf(v[j].z, v[j].w));
                #pragma unroll
                for (int off = 1; off < 16; off <<= 1)
                    m = fmaxf(m, __shfl_xor_sync(0xffffffffu, m, off));
                const float d0 = __shfl_sync(0xffffffffu, v[j].x, lane & 16);
                if (m > d0) local = row + 1;
            }
            #pragma unroll
            for (int off = 16; off; off >>= 1)
                local = max(local, __shfl_down_sync(0xffffffffu, local, off));
            if (lane == 0) s_red[w] = local;
        }
        __syncthreads();
        if (tid == 0) {
            int o = 0;
            #pragma unroll
            for (int i = 0; i < 16; i++) o = max(o, s_red[i]);
            s_olen = o;
        }
        __syncthreads();
        idx += min(s_olen, M_ - idx);
    }

    // ---------------- Phase 3: zero-fill tail of new_d ----------------
    {
        const float4 z = make_float4(0.f, 0.f, 0.f, 0.f);
        float* __restrict__ dst = out + ((size_t)b * M_ + idx) * V_;
        const int rem4 = (M_ - idx) * (V_ / 4);
        for (int i = tid; i < rem4; i += NT)
            ((float4*)dst)[i] = z;
    }
}

extern "C" void kernel_launch(void* const* d_in, const int* in_sizes, int n_in,
                              void* d_out, int out_size)
{
    (void)in_sizes; (void)n_in; (void)out_size;
    const float* decodings    = (const float*)d_in[0];
    // d_in[1] = variables : unused (new_v is all zeros)
    const int*   target_types = (const int*)d_in[2];
    const int*   spans        = (const int*)d_in[3];
    const float* te_table     = (const float*)d_in[4];
    const float* W_sem        = (const float*)d_in[5];
    const float* b_sem        = (const float*)d_in[6];
    const float* gumbel       = (const float*)d_in[7];
    float*       out          = (float*)d_out;

    fused_kernel<<<B_, NT>>>(
        decodings, target_types, spans, te_table, W_sem, b_sem, gumbel, out);
}